// round 1
// baseline (speedup 1.0000x reference)
#include <cuda_runtime.h>
#include <math.h>
#include <stdint.h>

// ---------------------------------------------------------------------------
// Problem constants
// ---------------------------------------------------------------------------
#define BATCH   8
#define CC      512
#define HW      48
#define NN      2304            // 48*48
#define BN      (BATCH * NN)    // 18432 total rows
#define MAXDEG  12
#define SCALE   0.044194173824159216f   // 1/sqrt(512)
#define LN_EPS  1e-5f

// ---------------------------------------------------------------------------
// Device scratch (static globals: allocation-free per harness rules)
// ---------------------------------------------------------------------------
__device__ float g_ssq [BN];
__device__ int   g_sidx[NN * 3];
__device__ int   g_fidx[BN * 3];
__device__ int   g_deg [BN];
__device__ int   g_src [BN * MAXDEG];
__device__ float g_gram[(size_t)BATCH * NN * NN];   // ~170 MB
__device__ float g_q   [(size_t)BN * CC];
__device__ float g_k   [(size_t)BN * CC];
__device__ float g_v   [(size_t)BN * CC];
__device__ float g_sk  [(size_t)BN * CC];
__device__ float g_h1  [(size_t)BN * CC];

// ---------------------------------------------------------------------------
// top-3 insertion with (value, index) lexicographic order — matches
// jax.lax.top_k tie-breaking (equal values -> lower index wins)
// ---------------------------------------------------------------------------
__device__ __forceinline__ void top3_insert(float d, int j,
                                            float& d0, int& j0,
                                            float& d1, int& j1,
                                            float& d2, int& j2) {
    bool b2 = (d < d2) || (d == d2 && j < j2);
    if (!b2) return;
    bool b1 = (d < d1) || (d == d1 && j < j1);
    if (b1) {
        d2 = d1; j2 = j1;
        bool b0 = (d < d0) || (d == d0 && j < j0);
        if (b0) { d1 = d0; j1 = j0; d0 = d; j0 = j; }
        else    { d1 = d;  j1 = j; }
    } else {
        d2 = d; j2 = j;
    }
}

// ---------------------------------------------------------------------------
// misc small kernels
// ---------------------------------------------------------------------------
__global__ void zero_deg_kernel() {
    int i = blockIdx.x * blockDim.x + threadIdx.x;
    if (i < BN) g_deg[i] = 0;
}

// per-row sum of squares of x (viewed [BN, CC]) : one warp per row
__global__ void ssq_kernel(const float* __restrict__ x) {
    int warp = (blockIdx.x * blockDim.x + threadIdx.x) >> 5;
    int lane = threadIdx.x & 31;
    if (warp >= BN) return;
    const float* row = x + (size_t)warp * CC;
    float s = 0.f;
    for (int c = lane; c < CC; c += 32) { float v = row[c]; s += v * v; }
    #pragma unroll
    for (int off = 16; off; off >>= 1) s += __shfl_xor_sync(0xffffffffu, s, off);
    if (lane == 0) g_ssq[warp] = s;
}

// spatial kNN (shared by all samples): one thread per node
__global__ void spatial_topk_kernel() {
    int i = blockIdx.x * blockDim.x + threadIdx.x;
    if (i >= NN) return;
    int yi = i / HW, xi = i % HW;
    float d0 = INFINITY, d1 = INFINITY, d2 = INFINITY;
    int   j0 = 0x7fffffff, j1 = 0x7fffffff, j2 = 0x7fffffff;
    for (int j = 0; j < NN; j++) {
        int yj = j / HW, xj = j % HW;
        int dy = yi - yj, dx = xi - xj;
        float d = sqrtf((float)(dy * dy + dx * dx));
        top3_insert(d, j, d0, j0, d1, j1, d2, j2);
    }
    g_sidx[i * 3 + 0] = j0;
    g_sidx[i * 3 + 1] = j1;
    g_sidx[i * 3 + 2] = j2;
}

// ---------------------------------------------------------------------------
// Gram per sample: G[b][i][j] = dot(x_i, x_j)   (64x64x16 SMEM tiling)
// ---------------------------------------------------------------------------
__global__ void gram_kernel(const float* __restrict__ X) {
    int b = blockIdx.z;
    const float* Xb = X + (size_t)b * NN * CC;
    __shared__ float As[16][64];
    __shared__ float Bs[16][64];
    int tid = threadIdx.x;
    int tx = tid & 15, ty = tid >> 4;
    int row0 = blockIdx.y * 64, col0 = blockIdx.x * 64;
    int lr = tid >> 2, lk = (tid & 3) << 2;
    float acc[4][4] = {};
    const float* Ap = Xb + (size_t)(row0 + lr) * CC + lk;
    const float* Bp = Xb + (size_t)(col0 + lr) * CC + lk;
    for (int k0 = 0; k0 < CC; k0 += 16) {
        float4 a4 = *(const float4*)(Ap + k0);
        As[lk + 0][lr] = a4.x; As[lk + 1][lr] = a4.y;
        As[lk + 2][lr] = a4.z; As[lk + 3][lr] = a4.w;
        float4 b4 = *(const float4*)(Bp + k0);
        Bs[lk + 0][lr] = b4.x; Bs[lk + 1][lr] = b4.y;
        Bs[lk + 2][lr] = b4.z; Bs[lk + 3][lr] = b4.w;
        __syncthreads();
        #pragma unroll
        for (int kk = 0; kk < 16; kk++) {
            float4 av = *(const float4*)(&As[kk][ty << 2]);
            float4 bv = *(const float4*)(&Bs[kk][tx << 2]);
            float a[4] = {av.x, av.y, av.z, av.w};
            float bb[4] = {bv.x, bv.y, bv.z, bv.w};
            #pragma unroll
            for (int i2 = 0; i2 < 4; i2++)
                #pragma unroll
                for (int j2 = 0; j2 < 4; j2++)
                    acc[i2][j2] += a[i2] * bb[j2];
        }
        __syncthreads();
    }
    float* Gb = g_gram + (size_t)b * NN * NN;
    #pragma unroll
    for (int i2 = 0; i2 < 4; i2++) {
        int r = row0 + (ty << 2) + i2;
        #pragma unroll
        for (int j2 = 0; j2 < 4; j2++) {
            int c = col0 + (tx << 2) + j2;
            Gb[(size_t)r * NN + c] = acc[i2][j2];
        }
    }
}

// feature kNN from Gram: one warp per row (b,i)
__global__ void feat_topk_kernel() {
    int winb = threadIdx.x >> 5, lane = threadIdx.x & 31;
    int row = blockIdx.x * 4 + winb;
    if (row >= BN) return;
    int b = row / NN;
    const float* grow = g_gram + (size_t)row * NN;
    const float* sq = g_ssq + b * NN;
    float si = g_ssq[row];
    float d0 = INFINITY, d1 = INFINITY, d2 = INFINITY;
    int   j0 = 0x7fffffff, j1 = 0x7fffffff, j2 = 0x7fffffff;
    for (int j = lane; j < NN; j += 32) {
        float dd = si + sq[j] - 2.0f * grow[j];
        float d = sqrtf(fmaxf(dd, 0.0f));
        top3_insert(d, j, d0, j0, d1, j1, d2, j2);
    }
    __shared__ float sd[4][96];
    __shared__ int   sj[4][96];
    sd[winb][lane * 3 + 0] = d0; sj[winb][lane * 3 + 0] = j0;
    sd[winb][lane * 3 + 1] = d1; sj[winb][lane * 3 + 1] = j1;
    sd[winb][lane * 3 + 2] = d2; sj[winb][lane * 3 + 2] = j2;
    __syncwarp();
    if (lane == 0) {
        float e0 = INFINITY, e1 = INFINITY, e2 = INFINITY;
        int   m0 = 0x7fffffff, m1 = 0x7fffffff, m2 = 0x7fffffff;
        for (int t = 0; t < 96; t++)
            top3_insert(sd[winb][t], sj[winb][t], e0, m0, e1, m1, e2, m2);
        g_fidx[row * 3 + 0] = m0;
        g_fidx[row * 3 + 1] = m1;
        g_fidx[row * 3 + 2] = m2;
    }
}

// adjacency build: edge i->f exists iff f in feat-top3(i) AND f in spatial-top3(i)
// stored transposed (per-target incoming source lists) for aggregation
__global__ void adj_kernel() {
    int row = blockIdx.x * blockDim.x + threadIdx.x;
    if (row >= BN) return;
    int b = row / NN, i = row % NN;
    int s0 = g_sidx[i * 3 + 0], s1 = g_sidx[i * 3 + 1], s2 = g_sidx[i * 3 + 2];
    #pragma unroll
    for (int e = 0; e < 3; e++) {
        int f = g_fidx[row * 3 + e];
        if (f == s0 || f == s1 || f == s2) {
            int tgt = b * NN + f;
            int pos = atomicAdd(&g_deg[tgt], 1);
            if (pos < MAXDEG) g_src[tgt * MAXDEG + pos] = row;
        }
    }
}

// ---------------------------------------------------------------------------
// dense GEMM: out[M=BN,512] = A[M,512] @ W[512,512] + bias
// ---------------------------------------------------------------------------
__global__ void gemm_bias_kernel(const float* __restrict__ A,
                                 const float* __restrict__ W,
                                 const float* __restrict__ bias,
                                 float* __restrict__ out) {
    __shared__ float As[16][64];
    __shared__ float Bs[16][64];
    int tid = threadIdx.x;
    int tx = tid & 15, ty = tid >> 4;
    int row0 = blockIdx.y * 64, col0 = blockIdx.x * 64;
    int lr = tid >> 2, lk = (tid & 3) << 2;
    int bk = tid >> 4, bc = (tid & 15) << 2;
    float acc[4][4] = {};
    const float* Ap = A + (size_t)(row0 + lr) * CC + lk;
    const float* Wp = W + (size_t)bk * CC + col0 + bc;
    for (int k0 = 0; k0 < CC; k0 += 16) {
        float4 a4 = *(const float4*)(Ap + k0);
        As[lk + 0][lr] = a4.x; As[lk + 1][lr] = a4.y;
        As[lk + 2][lr] = a4.z; As[lk + 3][lr] = a4.w;
        float4 b4 = *(const float4*)(Wp + (size_t)k0 * CC);
        *(float4*)(&Bs[bk][bc]) = b4;
        __syncthreads();
        #pragma unroll
        for (int kk = 0; kk < 16; kk++) {
            float4 av = *(const float4*)(&As[kk][ty << 2]);
            float4 bv = *(const float4*)(&Bs[kk][tx << 2]);
            float a[4] = {av.x, av.y, av.z, av.w};
            float bb[4] = {bv.x, bv.y, bv.z, bv.w};
            #pragma unroll
            for (int i2 = 0; i2 < 4; i2++)
                #pragma unroll
                for (int j2 = 0; j2 < 4; j2++)
                    acc[i2][j2] += a[i2] * bb[j2];
        }
        __syncthreads();
    }
    #pragma unroll
    for (int i2 = 0; i2 < 4; i2++) {
        int r = row0 + (ty << 2) + i2;
        #pragma unroll
        for (int j2 = 0; j2 < 4; j2++) {
            int c = col0 + (tx << 2) + j2;
            out[(size_t)r * CC + c] = acc[i2][j2] + bias[c];
        }
    }
}

// ---------------------------------------------------------------------------
// sparse attention + skip (+ optional ReLU/LN or sigmoid-gate epilogue)
// one block (128 threads) per target row t in [0, BN)
// ---------------------------------------------------------------------------
__global__ void attn1_kernel(const float* __restrict__ ln_g,
                             const float* __restrict__ ln_b) {
    int t = blockIdx.x;
    int tid = threadIdx.x, lane = tid & 31, w = tid >> 5;
    __shared__ float s_alpha[MAXDEG];
    __shared__ int   s_srcl[MAXDEG];
    __shared__ float red[128];
    int d = g_deg[t]; if (d > MAXDEG) d = MAXDEG;
    if (tid < d) s_srcl[tid] = g_src[t * MAXDEG + tid];
    __syncthreads();
    const float* qt = g_q + (size_t)t * CC;
    for (int e = w; e < d; e += 4) {
        const float* ks = g_k + (size_t)s_srcl[e] * CC;
        float p = 0.f;
        for (int c = lane; c < CC; c += 32) p += qt[c] * ks[c];
        #pragma unroll
        for (int off = 16; off; off >>= 1) p += __shfl_xor_sync(0xffffffffu, p, off);
        if (lane == 0) s_alpha[e] = p * SCALE;
    }
    __syncthreads();
    if (tid == 0) {
        float mx = -INFINITY;
        for (int e = 0; e < d; e++) mx = fmaxf(mx, s_alpha[e]);
        float sum = 0.f;
        for (int e = 0; e < d; e++) { float ex = expf(s_alpha[e] - mx); s_alpha[e] = ex; sum += ex; }
        float inv = 1.f / sum;
        for (int e = 0; e < d; e++) s_alpha[e] *= inv;
    }
    __syncthreads();
    float ov[4];
    #pragma unroll
    for (int r = 0; r < 4; r++) {
        int c = tid + 128 * r;
        float acc = g_sk[(size_t)t * CC + c];
        for (int e = 0; e < d; e++)
            acc += s_alpha[e] * g_v[(size_t)s_srcl[e] * CC + c];
        ov[r] = fmaxf(acc, 0.f);   // ReLU
    }
    // LayerNorm over the 512-row
    float ls = ov[0] + ov[1] + ov[2] + ov[3];
    float ls2 = ov[0]*ov[0] + ov[1]*ov[1] + ov[2]*ov[2] + ov[3]*ov[3];
    red[tid] = ls; __syncthreads();
    for (int off = 64; off; off >>= 1) { if (tid < off) red[tid] += red[tid + off]; __syncthreads(); }
    float S = red[0]; __syncthreads();
    red[tid] = ls2; __syncthreads();
    for (int off = 64; off; off >>= 1) { if (tid < off) red[tid] += red[tid + off]; __syncthreads(); }
    float S2 = red[0]; __syncthreads();
    float mu  = S * (1.f / CC);
    float var = S2 * (1.f / CC) - mu * mu;
    float inv = rsqrtf(var + LN_EPS);
    #pragma unroll
    for (int r = 0; r < 4; r++) {
        int c = tid + 128 * r;
        g_h1[(size_t)t * CC + c] = (ov[r] - mu) * inv * ln_g[c] + ln_b[c];
    }
}

__global__ void attn2_kernel(const float* __restrict__ x3,
                             float* __restrict__ out) {
    int t = blockIdx.x;
    int tid = threadIdx.x, lane = tid & 31, w = tid >> 5;
    __shared__ float s_alpha[MAXDEG];
    __shared__ int   s_srcl[MAXDEG];
    int d = g_deg[t]; if (d > MAXDEG) d = MAXDEG;
    if (tid < d) s_srcl[tid] = g_src[t * MAXDEG + tid];
    __syncthreads();
    const float* qt = g_q + (size_t)t * CC;
    for (int e = w; e < d; e += 4) {
        const float* ks = g_k + (size_t)s_srcl[e] * CC;
        float p = 0.f;
        for (int c = lane; c < CC; c += 32) p += qt[c] * ks[c];
        #pragma unroll
        for (int off = 16; off; off >>= 1) p += __shfl_xor_sync(0xffffffffu, p, off);
        if (lane == 0) s_alpha[e] = p * SCALE;
    }
    __syncthreads();
    if (tid == 0) {
        float mx = -INFINITY;
        for (int e = 0; e < d; e++) mx = fmaxf(mx, s_alpha[e]);
        float sum = 0.f;
        for (int e = 0; e < d; e++) { float ex = expf(s_alpha[e] - mx); s_alpha[e] = ex; sum += ex; }
        float inv = 1.f / sum;
        for (int e = 0; e < d; e++) s_alpha[e] *= inv;
    }
    __syncthreads();
    #pragma unroll
    for (int r = 0; r < 4; r++) {
        int c = tid + 128 * r;
        size_t idx = (size_t)t * CC + c;
        float acc = g_sk[idx];
        for (int e = 0; e < d; e++)
            acc += s_alpha[e] * g_v[(size_t)s_srcl[e] * CC + c];
        float sig = 1.f / (1.f + expf(-acc));
        out[idx] = x3[idx] * sig;
    }
}

// ---------------------------------------------------------------------------
// launch
// ---------------------------------------------------------------------------
extern "C" void kernel_launch(void* const* d_in, const int* in_sizes, int n_in,
                              void* d_out, int out_size) {
    const float* x3  = (const float*)d_in[0];
    const float* wq1 = (const float*)d_in[1];  const float* bq1 = (const float*)d_in[2];
    const float* wk1 = (const float*)d_in[3];  const float* bk1 = (const float*)d_in[4];
    const float* wv1 = (const float*)d_in[5];  const float* bv1 = (const float*)d_in[6];
    const float* ws1 = (const float*)d_in[7];  const float* bs1 = (const float*)d_in[8];
    const float* wq2 = (const float*)d_in[9];  const float* bq2 = (const float*)d_in[10];
    const float* wk2 = (const float*)d_in[11]; const float* bk2 = (const float*)d_in[12];
    const float* wv2 = (const float*)d_in[13]; const float* bv2 = (const float*)d_in[14];
    const float* ws2 = (const float*)d_in[15]; const float* bs2 = (const float*)d_in[16];
    const float* lng = (const float*)d_in[17]; const float* lnb = (const float*)d_in[18];
    float* out = (float*)d_out;

    float *pq, *pk, *pv, *psk, *ph1;
    cudaGetSymbolAddress((void**)&pq,  g_q);
    cudaGetSymbolAddress((void**)&pk,  g_k);
    cudaGetSymbolAddress((void**)&pv,  g_v);
    cudaGetSymbolAddress((void**)&psk, g_sk);
    cudaGetSymbolAddress((void**)&ph1, g_h1);

    // --- graph construction ---
    zero_deg_kernel<<<(BN + 255) / 256, 256>>>();
    ssq_kernel<<<BN / 8, 256>>>(x3);                 // 8 warps/block
    spatial_topk_kernel<<<(NN + 255) / 256, 256>>>();
    gram_kernel<<<dim3(NN / 64, NN / 64, BATCH), 256>>>(x3);
    feat_topk_kernel<<<BN / 4, 128>>>();
    adj_kernel<<<(BN + 255) / 256, 256>>>();

    dim3 ggrid(CC / 64, BN / 64);   // (8, 288)

    // --- conv1 ---
    gemm_bias_kernel<<<ggrid, 256>>>(x3, wq1, bq1, pq);
    gemm_bias_kernel<<<ggrid, 256>>>(x3, wk1, bk1, pk);
    gemm_bias_kernel<<<ggrid, 256>>>(x3, wv1, bv1, pv);
    gemm_bias_kernel<<<ggrid, 256>>>(x3, ws1, bs1, psk);
    attn1_kernel<<<BN, 128>>>(lng, lnb);

    // --- conv2 ---
    gemm_bias_kernel<<<ggrid, 256>>>(ph1, wq2, bq2, pq);
    gemm_bias_kernel<<<ggrid, 256>>>(ph1, wk2, bk2, pk);
    gemm_bias_kernel<<<ggrid, 256>>>(ph1, wv2, bv2, pv);
    gemm_bias_kernel<<<ggrid, 256>>>(ph1, ws2, bs2, psk);
    attn2_kernel<<<BN, 128>>>(x3, out);
}

// round 2
// speedup vs baseline: 1.4712x; 1.4712x over previous
#include <cuda_runtime.h>
#include <math.h>
#include <stdint.h>

// ---------------------------------------------------------------------------
// Problem constants
// ---------------------------------------------------------------------------
#define BATCH   8
#define CC      512
#define HW      48
#define NN      2304            // 48*48
#define BN      (BATCH * NN)    // 18432 total rows
#define MAXDEG  12
#define SCALE   0.044194173824159216f   // 1/sqrt(512)
#define LN_EPS  1e-5f

// ---------------------------------------------------------------------------
// Device scratch (static globals: allocation-free per harness rules)
// ---------------------------------------------------------------------------
__device__ float g_ssq [BN];
__device__ int   g_sidx[NN * 3];
__device__ int   g_fidx[BN * 3];
__device__ int   g_deg [BN];
__device__ int   g_src [BN * MAXDEG];
__device__ float g_gram[(size_t)BATCH * NN * NN];   // ~170 MB
__device__ float g_q   [(size_t)BN * CC];
__device__ float g_k   [(size_t)BN * CC];
__device__ float g_v   [(size_t)BN * CC];
__device__ float g_sk  [(size_t)BN * CC];
__device__ float g_h1  [(size_t)BN * CC];

// ---------------------------------------------------------------------------
// tf32 helpers (3xtf32 split-precision: fp32-class accuracy on tensor cores)
// ---------------------------------------------------------------------------
__device__ __forceinline__ uint32_t f2tf32(float x) {
    uint32_t r;
    asm("cvt.rna.tf32.f32 %0, %1;" : "=r"(r) : "f"(x));
    return r;
}

__device__ __forceinline__ void cvt_store(float* __restrict__ Sh,
                                          float* __restrict__ Sl,
                                          int off, float v) {
    uint32_t hb = f2tf32(v);
    float hf = __uint_as_float(hb);
    Sh[off] = hf;
    Sl[off] = __uint_as_float(f2tf32(v - hf));
}

__device__ __forceinline__ void mma8(float* c, const uint32_t* a,
                                     uint32_t b0, uint32_t b1) {
    asm volatile(
        "mma.sync.aligned.m16n8k8.row.col.f32.tf32.tf32.f32 "
        "{%0,%1,%2,%3},{%4,%5,%6,%7},{%8,%9},{%0,%1,%2,%3};"
        : "+f"(c[0]), "+f"(c[1]), "+f"(c[2]), "+f"(c[3])
        : "r"(a[0]), "r"(a[1]), "r"(a[2]), "r"(a[3]), "r"(b0), "r"(b1));
}

// ---------------------------------------------------------------------------
// top-3 insertion with (value, index) lexicographic order — matches
// jax.lax.top_k tie-breaking (equal values -> lower index wins)
// ---------------------------------------------------------------------------
__device__ __forceinline__ void top3_insert(float d, int j,
                                            float& d0, int& j0,
                                            float& d1, int& j1,
                                            float& d2, int& j2) {
    bool b2 = (d < d2) || (d == d2 && j < j2);
    if (!b2) return;
    bool b1 = (d < d1) || (d == d1 && j < j1);
    if (b1) {
        d2 = d1; j2 = j1;
        bool b0 = (d < d0) || (d == d0 && j < j0);
        if (b0) { d1 = d0; j1 = j0; d0 = d; j0 = j; }
        else    { d1 = d;  j1 = j; }
    } else {
        d2 = d; j2 = j;
    }
}

// ---------------------------------------------------------------------------
// misc small kernels
// ---------------------------------------------------------------------------
__global__ void zero_deg_kernel() {
    int i = blockIdx.x * blockDim.x + threadIdx.x;
    if (i < BN) g_deg[i] = 0;
}

// per-row sum of squares of x (viewed [BN, CC]) : one warp per row
__global__ void ssq_kernel(const float* __restrict__ x) {
    int warp = (blockIdx.x * blockDim.x + threadIdx.x) >> 5;
    int lane = threadIdx.x & 31;
    if (warp >= BN) return;
    const float* row = x + (size_t)warp * CC;
    float s = 0.f;
    for (int c = lane; c < CC; c += 32) { float v = row[c]; s += v * v; }
    #pragma unroll
    for (int off = 16; off; off >>= 1) s += __shfl_xor_sync(0xffffffffu, s, off);
    if (lane == 0) g_ssq[warp] = s;
}

// spatial kNN (shared by all samples): one thread per node
__global__ void spatial_topk_kernel() {
    int i = blockIdx.x * blockDim.x + threadIdx.x;
    if (i >= NN) return;
    int yi = i / HW, xi = i % HW;
    float d0 = INFINITY, d1 = INFINITY, d2 = INFINITY;
    int   j0 = 0x7fffffff, j1 = 0x7fffffff, j2 = 0x7fffffff;
    for (int j = 0; j < NN; j++) {
        int yj = j / HW, xj = j % HW;
        int dy = yi - yj, dx = xi - xj;
        float d = sqrtf((float)(dy * dy + dx * dx));
        top3_insert(d, j, d0, j0, d1, j1, d2, j2);
    }
    g_sidx[i * 3 + 0] = j0;
    g_sidx[i * 3 + 1] = j1;
    g_sidx[i * 3 + 2] = j2;
}

// ---------------------------------------------------------------------------
// Gram per sample via 3xtf32 tensor-core MMA:
// G[b][i][j] = dot(x_i, x_j). Block tile 128x128x16, 4 warps, warp tile 64x64.
// SMEM strides: 20 floats/row -> fragment bank = (4m+k)%32, conflict-free.
// ---------------------------------------------------------------------------
__global__ void __launch_bounds__(128) gram3_kernel(const float* __restrict__ X) {
    __shared__ float Ah[128 * 20], Al[128 * 20];
    __shared__ float Bh[128 * 20], Bl[128 * 20];
    const float* Xb = X + (size_t)blockIdx.z * NN * CC;
    int tid = threadIdx.x;
    int warp = tid >> 5, lane = tid & 31;
    int wm = (warp >> 1) * 64, wn = (warp & 1) * 64;
    int g = lane >> 2, t4 = lane & 3;
    int row0 = blockIdx.y * 128, col0 = blockIdx.x * 128;
    float acc[4][8][4] = {};

    for (int k0 = 0; k0 < CC; k0 += 16) {
        #pragma unroll
        for (int i = 0; i < 4; i++) {
            int idx = tid + 128 * i;
            int m = idx >> 2, k4 = (idx & 3) << 2;
            int o = m * 20 + k4;
            float4 va = *(const float4*)(Xb + (size_t)(row0 + m) * CC + k0 + k4);
            cvt_store(Ah, Al, o + 0, va.x); cvt_store(Ah, Al, o + 1, va.y);
            cvt_store(Ah, Al, o + 2, va.z); cvt_store(Ah, Al, o + 3, va.w);
            float4 vb = *(const float4*)(Xb + (size_t)(col0 + m) * CC + k0 + k4);
            cvt_store(Bh, Bl, o + 0, vb.x); cvt_store(Bh, Bl, o + 1, vb.y);
            cvt_store(Bh, Bl, o + 2, vb.z); cvt_store(Bh, Bl, o + 3, vb.w);
        }
        __syncthreads();
        #pragma unroll
        for (int kk = 0; kk < 16; kk += 8) {
            uint32_t ah[4][4], al[4][4];
            #pragma unroll
            for (int mt = 0; mt < 4; mt++) {
                int r0i = (wm + mt * 16 + g) * 20 + kk + t4;
                int r1i = r0i + 8 * 20;
                ah[mt][0] = __float_as_uint(Ah[r0i]);
                ah[mt][1] = __float_as_uint(Ah[r1i]);
                ah[mt][2] = __float_as_uint(Ah[r0i + 4]);
                ah[mt][3] = __float_as_uint(Ah[r1i + 4]);
                al[mt][0] = __float_as_uint(Al[r0i]);
                al[mt][1] = __float_as_uint(Al[r1i]);
                al[mt][2] = __float_as_uint(Al[r0i + 4]);
                al[mt][3] = __float_as_uint(Al[r1i + 4]);
            }
            #pragma unroll
            for (int nt = 0; nt < 8; nt++) {
                int nb = (wn + nt * 8 + g) * 20 + kk + t4;   // Bs[n][k] layout
                uint32_t bh0 = __float_as_uint(Bh[nb]);
                uint32_t bh1 = __float_as_uint(Bh[nb + 4]);
                uint32_t bl0 = __float_as_uint(Bl[nb]);
                uint32_t bl1 = __float_as_uint(Bl[nb + 4]);
                #pragma unroll
                for (int mt = 0; mt < 4; mt++) {
                    mma8(acc[mt][nt], ah[mt], bh0, bh1);
                    mma8(acc[mt][nt], ah[mt], bl0, bl1);
                    mma8(acc[mt][nt], al[mt], bh0, bh1);
                }
            }
        }
        __syncthreads();
    }
    float* Gb = g_gram + (size_t)blockIdx.z * NN * NN;
    #pragma unroll
    for (int mt = 0; mt < 4; mt++) {
        int r = row0 + wm + mt * 16 + g;
        #pragma unroll
        for (int nt = 0; nt < 8; nt++) {
            int c = col0 + wn + nt * 8 + 2 * t4;
            Gb[(size_t)r * NN + c]           = acc[mt][nt][0];
            Gb[(size_t)r * NN + c + 1]       = acc[mt][nt][1];
            Gb[(size_t)(r + 8) * NN + c]     = acc[mt][nt][2];
            Gb[(size_t)(r + 8) * NN + c + 1] = acc[mt][nt][3];
        }
    }
}

// ---------------------------------------------------------------------------
// Dense GEMM via 3xtf32: out[BN,512] = A[BN,512] @ W[512,512] + bias
// B tile SMEM stride 136 -> fragment bank = (8k+n)%32, conflict-free.
// ---------------------------------------------------------------------------
__global__ void __launch_bounds__(128) gemm3_kernel(const float* __restrict__ A,
                                                    const float* __restrict__ W,
                                                    const float* __restrict__ bias,
                                                    float* __restrict__ out) {
    __shared__ float Ah[128 * 20], Al[128 * 20];
    __shared__ float Bh[16 * 136], Bl[16 * 136];
    int tid = threadIdx.x;
    int warp = tid >> 5, lane = tid & 31;
    int wm = (warp >> 1) * 64, wn = (warp & 1) * 64;
    int g = lane >> 2, t4 = lane & 3;
    int row0 = blockIdx.y * 128, col0 = blockIdx.x * 128;
    float acc[4][8][4] = {};

    for (int k0 = 0; k0 < CC; k0 += 16) {
        #pragma unroll
        for (int i = 0; i < 4; i++) {
            int idx = tid + 128 * i;
            int m = idx >> 2, k4 = (idx & 3) << 2;
            int o = m * 20 + k4;
            float4 va = *(const float4*)(A + (size_t)(row0 + m) * CC + k0 + k4);
            cvt_store(Ah, Al, o + 0, va.x); cvt_store(Ah, Al, o + 1, va.y);
            cvt_store(Ah, Al, o + 2, va.z); cvt_store(Ah, Al, o + 3, va.w);
        }
        #pragma unroll
        for (int i = 0; i < 4; i++) {
            int idx = tid + 128 * i;
            int k = idx >> 5, n4 = (idx & 31) << 2;
            int o = k * 136 + n4;
            float4 vb = *(const float4*)(W + (size_t)(k0 + k) * CC + col0 + n4);
            cvt_store(Bh, Bl, o + 0, vb.x); cvt_store(Bh, Bl, o + 1, vb.y);
            cvt_store(Bh, Bl, o + 2, vb.z); cvt_store(Bh, Bl, o + 3, vb.w);
        }
        __syncthreads();
        #pragma unroll
        for (int kk = 0; kk < 16; kk += 8) {
            uint32_t ah[4][4], al[4][4];
            #pragma unroll
            for (int mt = 0; mt < 4; mt++) {
                int r0i = (wm + mt * 16 + g) * 20 + kk + t4;
                int r1i = r0i + 8 * 20;
                ah[mt][0] = __float_as_uint(Ah[r0i]);
                ah[mt][1] = __float_as_uint(Ah[r1i]);
                ah[mt][2] = __float_as_uint(Ah[r0i + 4]);
                ah[mt][3] = __float_as_uint(Ah[r1i + 4]);
                al[mt][0] = __float_as_uint(Al[r0i]);
                al[mt][1] = __float_as_uint(Al[r1i]);
                al[mt][2] = __float_as_uint(Al[r0i + 4]);
                al[mt][3] = __float_as_uint(Al[r1i + 4]);
            }
            #pragma unroll
            for (int nt = 0; nt < 8; nt++) {
                int nc = wn + nt * 8 + g;
                int kb = (kk + t4) * 136 + nc;
                uint32_t bh0 = __float_as_uint(Bh[kb]);
                uint32_t bh1 = __float_as_uint(Bh[kb + 4 * 136]);
                uint32_t bl0 = __float_as_uint(Bl[kb]);
                uint32_t bl1 = __float_as_uint(Bl[kb + 4 * 136]);
                #pragma unroll
                for (int mt = 0; mt < 4; mt++) {
                    mma8(acc[mt][nt], ah[mt], bh0, bh1);
                    mma8(acc[mt][nt], ah[mt], bl0, bl1);
                    mma8(acc[mt][nt], al[mt], bh0, bh1);
                }
            }
        }
        __syncthreads();
    }
    #pragma unroll
    for (int mt = 0; mt < 4; mt++) {
        int r = row0 + wm + mt * 16 + g;
        #pragma unroll
        for (int nt = 0; nt < 8; nt++) {
            int c = col0 + wn + nt * 8 + 2 * t4;
            float b0v = bias[c], b1v = bias[c + 1];
            out[(size_t)r * CC + c]           = acc[mt][nt][0] + b0v;
            out[(size_t)r * CC + c + 1]       = acc[mt][nt][1] + b1v;
            out[(size_t)(r + 8) * CC + c]     = acc[mt][nt][2] + b0v;
            out[(size_t)(r + 8) * CC + c + 1] = acc[mt][nt][3] + b1v;
        }
    }
}

// feature kNN from Gram: one warp per row (b,i)
__global__ void feat_topk_kernel() {
    int winb = threadIdx.x >> 5, lane = threadIdx.x & 31;
    int row = blockIdx.x * 4 + winb;
    if (row >= BN) return;
    int b = row / NN;
    const float* grow = g_gram + (size_t)row * NN;
    const float* sq = g_ssq + b * NN;
    float si = g_ssq[row];
    float d0 = INFINITY, d1 = INFINITY, d2 = INFINITY;
    int   j0 = 0x7fffffff, j1 = 0x7fffffff, j2 = 0x7fffffff;
    for (int j = lane; j < NN; j += 32) {
        float dd = si + sq[j] - 2.0f * grow[j];
        float d = sqrtf(fmaxf(dd, 0.0f));
        top3_insert(d, j, d0, j0, d1, j1, d2, j2);
    }
    __shared__ float sd[4][96];
    __shared__ int   sj[4][96];
    sd[winb][lane * 3 + 0] = d0; sj[winb][lane * 3 + 0] = j0;
    sd[winb][lane * 3 + 1] = d1; sj[winb][lane * 3 + 1] = j1;
    sd[winb][lane * 3 + 2] = d2; sj[winb][lane * 3 + 2] = j2;
    __syncwarp();
    if (lane == 0) {
        float e0 = INFINITY, e1 = INFINITY, e2 = INFINITY;
        int   m0 = 0x7fffffff, m1 = 0x7fffffff, m2 = 0x7fffffff;
        for (int t = 0; t < 96; t++)
            top3_insert(sd[winb][t], sj[winb][t], e0, m0, e1, m1, e2, m2);
        g_fidx[row * 3 + 0] = m0;
        g_fidx[row * 3 + 1] = m1;
        g_fidx[row * 3 + 2] = m2;
    }
}

// adjacency build: edge i->f exists iff f in feat-top3(i) AND f in spatial-top3(i)
// stored transposed (per-target incoming source lists) for aggregation
__global__ void adj_kernel() {
    int row = blockIdx.x * blockDim.x + threadIdx.x;
    if (row >= BN) return;
    int b = row / NN, i = row % NN;
    int s0 = g_sidx[i * 3 + 0], s1 = g_sidx[i * 3 + 1], s2 = g_sidx[i * 3 + 2];
    #pragma unroll
    for (int e = 0; e < 3; e++) {
        int f = g_fidx[row * 3 + e];
        if (f == s0 || f == s1 || f == s2) {
            int tgt = b * NN + f;
            int pos = atomicAdd(&g_deg[tgt], 1);
            if (pos < MAXDEG) g_src[tgt * MAXDEG + pos] = row;
        }
    }
}

// ---------------------------------------------------------------------------
// sparse attention + skip; one block (128 threads) per target row
// ---------------------------------------------------------------------------
__global__ void attn1_kernel(const float* __restrict__ ln_g,
                             const float* __restrict__ ln_b) {
    int t = blockIdx.x;
    int tid = threadIdx.x, lane = tid & 31, w = tid >> 5;
    __shared__ float s_alpha[MAXDEG];
    __shared__ int   s_srcl[MAXDEG];
    __shared__ float red[128];
    int d = g_deg[t]; if (d > MAXDEG) d = MAXDEG;
    if (tid < d) s_srcl[tid] = g_src[t * MAXDEG + tid];
    __syncthreads();
    const float* qt = g_q + (size_t)t * CC;
    for (int e = w; e < d; e += 4) {
        const float* ks = g_k + (size_t)s_srcl[e] * CC;
        float p = 0.f;
        for (int c = lane; c < CC; c += 32) p += qt[c] * ks[c];
        #pragma unroll
        for (int off = 16; off; off >>= 1) p += __shfl_xor_sync(0xffffffffu, p, off);
        if (lane == 0) s_alpha[e] = p * SCALE;
    }
    __syncthreads();
    if (tid == 0) {
        float mx = -INFINITY;
        for (int e = 0; e < d; e++) mx = fmaxf(mx, s_alpha[e]);
        float sum = 0.f;
        for (int e = 0; e < d; e++) { float ex = expf(s_alpha[e] - mx); s_alpha[e] = ex; sum += ex; }
        float inv = 1.f / sum;
        for (int e = 0; e < d; e++) s_alpha[e] *= inv;
    }
    __syncthreads();
    float ov[4];
    #pragma unroll
    for (int r = 0; r < 4; r++) {
        int c = tid + 128 * r;
        float acc = g_sk[(size_t)t * CC + c];
        for (int e = 0; e < d; e++)
            acc += s_alpha[e] * g_v[(size_t)s_srcl[e] * CC + c];
        ov[r] = fmaxf(acc, 0.f);   // ReLU
    }
    float ls = ov[0] + ov[1] + ov[2] + ov[3];
    float ls2 = ov[0]*ov[0] + ov[1]*ov[1] + ov[2]*ov[2] + ov[3]*ov[3];
    red[tid] = ls; __syncthreads();
    for (int off = 64; off; off >>= 1) { if (tid < off) red[tid] += red[tid + off]; __syncthreads(); }
    float S = red[0]; __syncthreads();
    red[tid] = ls2; __syncthreads();
    for (int off = 64; off; off >>= 1) { if (tid < off) red[tid] += red[tid + off]; __syncthreads(); }
    float S2 = red[0]; __syncthreads();
    float mu  = S * (1.f / CC);
    float var = S2 * (1.f / CC) - mu * mu;
    float inv = rsqrtf(var + LN_EPS);
    #pragma unroll
    for (int r = 0; r < 4; r++) {
        int c = tid + 128 * r;
        g_h1[(size_t)t * CC + c] = (ov[r] - mu) * inv * ln_g[c] + ln_b[c];
    }
}

__global__ void attn2_kernel(const float* __restrict__ x3,
                             float* __restrict__ out) {
    int t = blockIdx.x;
    int tid = threadIdx.x, lane = tid & 31, w = tid >> 5;
    __shared__ float s_alpha[MAXDEG];
    __shared__ int   s_srcl[MAXDEG];
    int d = g_deg[t]; if (d > MAXDEG) d = MAXDEG;
    if (tid < d) s_srcl[tid] = g_src[t * MAXDEG + tid];
    __syncthreads();
    const float* qt = g_q + (size_t)t * CC;
    for (int e = w; e < d; e += 4) {
        const float* ks = g_k + (size_t)s_srcl[e] * CC;
        float p = 0.f;
        for (int c = lane; c < CC; c += 32) p += qt[c] * ks[c];
        #pragma unroll
        for (int off = 16; off; off >>= 1) p += __shfl_xor_sync(0xffffffffu, p, off);
        if (lane == 0) s_alpha[e] = p * SCALE;
    }
    __syncthreads();
    if (tid == 0) {
        float mx = -INFINITY;
        for (int e = 0; e < d; e++) mx = fmaxf(mx, s_alpha[e]);
        float sum = 0.f;
        for (int e = 0; e < d; e++) { float ex = expf(s_alpha[e] - mx); s_alpha[e] = ex; sum += ex; }
        float inv = 1.f / sum;
        for (int e = 0; e < d; e++) s_alpha[e] *= inv;
    }
    __syncthreads();
    #pragma unroll
    for (int r = 0; r < 4; r++) {
        int c = tid + 128 * r;
        size_t idx = (size_t)t * CC + c;
        float acc = g_sk[idx];
        for (int e = 0; e < d; e++)
            acc += s_alpha[e] * g_v[(size_t)s_srcl[e] * CC + c];
        float sig = 1.f / (1.f + expf(-acc));
        out[idx] = x3[idx] * sig;
    }
}

// ---------------------------------------------------------------------------
// launch
// ---------------------------------------------------------------------------
extern "C" void kernel_launch(void* const* d_in, const int* in_sizes, int n_in,
                              void* d_out, int out_size) {
    const float* x3  = (const float*)d_in[0];
    const float* wq1 = (const float*)d_in[1];  const float* bq1 = (const float*)d_in[2];
    const float* wk1 = (const float*)d_in[3];  const float* bk1 = (const float*)d_in[4];
    const float* wv1 = (const float*)d_in[5];  const float* bv1 = (const float*)d_in[6];
    const float* ws1 = (const float*)d_in[7];  const float* bs1 = (const float*)d_in[8];
    const float* wq2 = (const float*)d_in[9];  const float* bq2 = (const float*)d_in[10];
    const float* wk2 = (const float*)d_in[11]; const float* bk2 = (const float*)d_in[12];
    const float* wv2 = (const float*)d_in[13]; const float* bv2 = (const float*)d_in[14];
    const float* ws2 = (const float*)d_in[15]; const float* bs2 = (const float*)d_in[16];
    const float* lng = (const float*)d_in[17]; const float* lnb = (const float*)d_in[18];
    float* out = (float*)d_out;

    float *pq, *pk, *pv, *psk, *ph1;
    cudaGetSymbolAddress((void**)&pq,  g_q);
    cudaGetSymbolAddress((void**)&pk,  g_k);
    cudaGetSymbolAddress((void**)&pv,  g_v);
    cudaGetSymbolAddress((void**)&psk, g_sk);
    cudaGetSymbolAddress((void**)&ph1, g_h1);

    // --- graph construction ---
    zero_deg_kernel<<<(BN + 255) / 256, 256>>>();
    ssq_kernel<<<BN / 8, 256>>>(x3);
    spatial_topk_kernel<<<(NN + 255) / 256, 256>>>();
    gram3_kernel<<<dim3(NN / 128, NN / 128, BATCH), 128>>>(x3);
    feat_topk_kernel<<<BN / 4, 128>>>();
    adj_kernel<<<(BN + 255) / 256, 256>>>();

    dim3 ggrid(CC / 128, BN / 128);   // (4, 144)

    // --- conv1 ---
    gemm3_kernel<<<ggrid, 128>>>(x3, wq1, bq1, pq);
    gemm3_kernel<<<ggrid, 128>>>(x3, wk1, bk1, pk);
    gemm3_kernel<<<ggrid, 128>>>(x3, wv1, bv1, pv);
    gemm3_kernel<<<ggrid, 128>>>(x3, ws1, bs1, psk);
    attn1_kernel<<<BN, 128>>>(lng, lnb);

    // --- conv2 ---
    gemm3_kernel<<<ggrid, 128>>>(ph1, wq2, bq2, pq);
    gemm3_kernel<<<ggrid, 128>>>(ph1, wk2, bk2, pk);
    gemm3_kernel<<<ggrid, 128>>>(ph1, wv2, bv2, pv);
    gemm3_kernel<<<ggrid, 128>>>(ph1, ws2, bs2, psk);
    attn2_kernel<<<BN, 128>>>(x3, out);
}